// round 1
// baseline (speedup 1.0000x reference)
#include <cuda_runtime.h>

// Problem constants
#define TT  2048
#define BB  2
#define DD  512
#define NHH 8
#define HDD 64

// flattened weight offsets
#define OFF_INW   0
#define OFF_OUTW  786432
#define OFF_POSW  1048576
#define OFF_INB   1310720
#define OFF_OUTB  1312256
#define OFF_POSB  1312768
#define OFF_RWB   1313280
#define OFF_RRB   1313792
#define N_W       1314304

// Scratch (allocation-free: __device__ globals)
__device__ float g_w[N_W];
__device__ float g_qkv[(size_t)TT * BB * 3 * DD];   // [T,B,3D]
__device__ float g_r[(size_t)TT * DD];              // [T,D]
__device__ float g_att[(size_t)TT * BB * DD];       // [T,B,D]

// ---------------------------------------------------------------------------
// 1) Bayesian weight sample: w = mu + softplus(rho) * eps
// ---------------------------------------------------------------------------
__global__ void k_sample_w(const float* __restrict__ mu,
                           const float* __restrict__ rho,
                           const float* __restrict__ eps,
                           float* __restrict__ w, int n) {
    int i = blockIdx.x * blockDim.x + threadIdx.x;
    if (i < n) {
        float r  = rho[i];
        float sp = (r > 20.f) ? r : log1pf(expf(r));
        w[i] = fmaf(sp, eps[i], mu[i]);
    }
}

// ---------------------------------------------------------------------------
// 2) C[M,N] = A[M,K] @ W[N,K]^T + bias[N]     (all fp32, K % 16 == 0,
//    M % 64 == 0, N % 64 == 0)
//    64x64 tile, BK=16, 256 threads, 4x4 micro-tile per thread.
// ---------------------------------------------------------------------------
__global__ __launch_bounds__(256)
void k_gemm(const float* __restrict__ A, const float* __restrict__ W,
            const float* __restrict__ bias, float* __restrict__ C,
            int M, int N, int K) {
    __shared__ float As[16][68];
    __shared__ float Bs[16][68];
    const int tid = threadIdx.x;
    const int tx = tid & 15, ty = tid >> 4;
    const int m0 = blockIdx.y * 64, n0 = blockIdx.x * 64;
    const int mm = tid >> 2;            // 0..63
    const int kk = (tid & 3) << 2;      // 0,4,8,12

    float acc[4][4] = {};

    for (int k0 = 0; k0 < K; k0 += 16) {
        float4 av = *(const float4*)(A + (size_t)(m0 + mm) * K + k0 + kk);
        float4 bv = *(const float4*)(W + (size_t)(n0 + mm) * K + k0 + kk);
        As[kk + 0][mm] = av.x; As[kk + 1][mm] = av.y;
        As[kk + 2][mm] = av.z; As[kk + 3][mm] = av.w;
        Bs[kk + 0][mm] = bv.x; Bs[kk + 1][mm] = bv.y;
        Bs[kk + 2][mm] = bv.z; Bs[kk + 3][mm] = bv.w;
        __syncthreads();
#pragma unroll
        for (int k = 0; k < 16; k++) {
            float4 a4 = *(const float4*)&As[k][ty * 4];
            float4 b4 = *(const float4*)&Bs[k][tx * 4];
            float aa[4] = {a4.x, a4.y, a4.z, a4.w};
            float bb[4] = {b4.x, b4.y, b4.z, b4.w};
#pragma unroll
            for (int u = 0; u < 4; u++)
#pragma unroll
                for (int v = 0; v < 4; v++)
                    acc[u][v] = fmaf(aa[u], bb[v], acc[u][v]);
        }
        __syncthreads();
    }

#pragma unroll
    for (int u = 0; u < 4; u++) {
        int m = m0 + ty * 4 + u;
#pragma unroll
        for (int v = 0; v < 4; v++) {
            int n = n0 + tx * 4 + v;
            C[(size_t)m * N + n] = acc[u][v] + bias[n];
        }
    }
}

// ---------------------------------------------------------------------------
// 3) Attention. One block per (query i, batch b, head n).
//    Causal + rel-shift:  score[i,j] = 0.125*((q_i+rwb)·k_j + (q_i+rrb)·r_m),
//    m = j - i + T - 1, valid (unmasked) only for j <= i.
// ---------------------------------------------------------------------------
__global__ __launch_bounds__(256)
void k_attn(const float* __restrict__ qkv, const float* __restrict__ r,
            const float* __restrict__ w, float* __restrict__ att) {
    const int i = blockIdx.x, b = blockIdx.y, n = blockIdx.z;
    const int tid = threadIdx.x;

    __shared__ float q1[HDD], q2[HDD];
    __shared__ float sc[TT];
    __shared__ float redv[256];
    __shared__ float red8[8];
    __shared__ float bval;

    const float* qrow = qkv + ((size_t)i * BB + b) * (3 * DD) + n * HDD;
    if (tid < HDD) {
        float qv = qrow[tid];
        q1[tid] = qv + w[OFF_RWB + n * HDD + tid];
        q2[tid] = qv + w[OFF_RRB + n * HDD + tid];
    }
    __syncthreads();

    const float4* q14 = (const float4*)q1;
    const float4* q24 = (const float4*)q2;
    const size_t kstride = (size_t)BB * 3 * DD;
    const float* kbase = qkv + (size_t)b * 3 * DD + DD + n * HDD;
    const float* rbase = r + (size_t)(TT - 1 - i) * DD + n * HDD;

    // scores for j in [0, i]
    for (int j = tid; j <= i; j += 256) {
        const float4* kp = (const float4*)(kbase + (size_t)j * kstride);
        const float4* rp = (const float4*)(rbase + (size_t)j * DD);
        float s = 0.f;
#pragma unroll
        for (int d = 0; d < 16; d++) {
            float4 kv = kp[d], rv = rp[d], a = q14[d], c = q24[d];
            s = fmaf(a.x, kv.x, s); s = fmaf(a.y, kv.y, s);
            s = fmaf(a.z, kv.z, s); s = fmaf(a.w, kv.w, s);
            s = fmaf(c.x, rv.x, s); s = fmaf(c.y, rv.y, s);
            s = fmaf(c.z, rv.z, s); s = fmaf(c.w, rv.w, s);
        }
        sc[j] = s * 0.125f;
    }
    __syncthreads();

    // block max
    float m = -3.4e38f;
    for (int j = tid; j <= i; j += 256) m = fmaxf(m, sc[j]);
#pragma unroll
    for (int o = 16; o > 0; o >>= 1)
        m = fmaxf(m, __shfl_xor_sync(0xffffffffu, m, o));
    if ((tid & 31) == 0) red8[tid >> 5] = m;
    __syncthreads();
    if (tid < 8) {
        float v = red8[tid];
#pragma unroll
        for (int o = 4; o > 0; o >>= 1)
            v = fmaxf(v, __shfl_xor_sync(0xffu, v, o));
        if (tid == 0) bval = v;
    }
    __syncthreads();
    m = bval;

    // exp + block sum
    float ss = 0.f;
    for (int j = tid; j <= i; j += 256) {
        float e = __expf(sc[j] - m);
        sc[j] = e;
        ss += e;
    }
#pragma unroll
    for (int o = 16; o > 0; o >>= 1)
        ss += __shfl_xor_sync(0xffffffffu, ss, o);
    if ((tid & 31) == 0) red8[tid >> 5] = ss;
    __syncthreads();
    if (tid < 8) {
        float v = red8[tid];
#pragma unroll
        for (int o = 4; o > 0; o >>= 1)
            v += __shfl_xor_sync(0xffu, v, o);
        if (tid == 0) bval = v;
    }
    __syncthreads();
    const float inv = 1.f / bval;

    // p @ v : 4 j-groups x 64 dims
    const int d = tid & 63, g = tid >> 6;
    const float* vb = qkv + (size_t)b * 3 * DD + 2 * DD + n * HDD + d;
    float acc = 0.f;
    for (int j = g; j <= i; j += 4)
        acc = fmaf(sc[j], vb[(size_t)j * kstride], acc);
    redv[tid] = acc;
    __syncthreads();
    if (g == 0) {
        float a = redv[d] + redv[64 + d] + redv[128 + d] + redv[192 + d];
        att[((size_t)i * BB + b) * DD + n * HDD + d] = a * inv;
    }
}

// ---------------------------------------------------------------------------
// Launch. Inputs (metadata order): input, pos, attn_mask(unused), mu, rho, eps
// ---------------------------------------------------------------------------
extern "C" void kernel_launch(void* const* d_in, const int* in_sizes, int n_in,
                              void* d_out, int out_size) {
    const float* input = (const float*)d_in[0];
    const float* pos   = (const float*)d_in[1];
    const float* mu    = (const float*)d_in[3];
    const float* rho   = (const float*)d_in[4];
    const float* eps   = (const float*)d_in[5];
    float* out = (float*)d_out;

    float *w, *qkv, *r, *att;
    cudaGetSymbolAddress((void**)&w,   g_w);
    cudaGetSymbolAddress((void**)&qkv, g_qkv);
    cudaGetSymbolAddress((void**)&r,   g_r);
    cudaGetSymbolAddress((void**)&att, g_att);

    k_sample_w<<<(N_W + 255) / 256, 256>>>(mu, rho, eps, w, N_W);

    // qkv = input @ in_w^T + in_b      [4096,512]x[1536,512]^T
    k_gemm<<<dim3(1536 / 64, 4096 / 64), 256>>>(input, w + OFF_INW, w + OFF_INB,
                                                qkv, TT * BB, 3 * DD, DD);
    // r = pos @ pos_w^T + pos_b        [2048,512]x[512,512]^T
    k_gemm<<<dim3(512 / 64, 2048 / 64), 256>>>(pos, w + OFF_POSW, w + OFF_POSB,
                                               r, TT, DD, DD);
    // attention
    k_attn<<<dim3(TT, BB, NHH), 256>>>(qkv, r, w, att);

    // out = att @ out_w^T + out_b      [4096,512]x[512,512]^T
    k_gemm<<<dim3(512 / 64, 4096 / 64), 256>>>(att, w + OFF_OUTW, w + OFF_OUTB,
                                               out, TT * BB, DD, DD);
}

// round 2
// speedup vs baseline: 10.5883x; 10.5883x over previous
#include <cuda_runtime.h>
#include <math.h>

// Problem constants
#define TT  2048
#define BB  2
#define DD  512
#define NHH 8
#define HDD 64

// flash tile sizes
#define BM 64
#define BN 64

// flattened weight offsets
#define OFF_INW   0
#define OFF_OUTW  786432
#define OFF_POSW  1048576
#define OFF_INB   1310720
#define OFF_OUTB  1312256
#define OFF_POSB  1312768
#define OFF_RWB   1313280
#define OFF_RRB   1313792
#define N_W       1314304

// Scratch (allocation-free: __device__ globals)
__device__ float g_w[N_W];
__device__ float g_qkv[(size_t)TT * BB * 3 * DD];   // [T,B,3D]
__device__ float g_r[(size_t)TT * DD];              // [T,D]
__device__ float g_att[(size_t)TT * BB * DD];       // [T,B,D]

// ---------------------------------------------------------------------------
// 1) Bayesian weight sample: w = mu + softplus(rho) * eps
// ---------------------------------------------------------------------------
__global__ void k_sample_w(const float* __restrict__ mu,
                           const float* __restrict__ rho,
                           const float* __restrict__ eps,
                           float* __restrict__ w, int n) {
    int i = blockIdx.x * blockDim.x + threadIdx.x;
    if (i < n) {
        float r  = rho[i];
        float sp = (r > 20.f) ? r : log1pf(expf(r));
        w[i] = fmaf(sp, eps[i], mu[i]);
    }
}

// ---------------------------------------------------------------------------
// 2) C[M,N] = A[M,K] @ W[N,K]^T + bias[N]   (fp32; K%16==0, M%64==0, N%64==0)
// ---------------------------------------------------------------------------
__global__ __launch_bounds__(256)
void k_gemm(const float* __restrict__ A, const float* __restrict__ W,
            const float* __restrict__ bias, float* __restrict__ C,
            int M, int N, int K) {
    __shared__ float As[16][68];
    __shared__ float Bs[16][68];
    const int tid = threadIdx.x;
    const int tx = tid & 15, ty = tid >> 4;
    const int m0 = blockIdx.y * 64, n0 = blockIdx.x * 64;
    const int mm = tid >> 2;
    const int kk = (tid & 3) << 2;

    float acc[4][4] = {};

    for (int k0 = 0; k0 < K; k0 += 16) {
        float4 av = *(const float4*)(A + (size_t)(m0 + mm) * K + k0 + kk);
        float4 bv = *(const float4*)(W + (size_t)(n0 + mm) * K + k0 + kk);
        As[kk + 0][mm] = av.x; As[kk + 1][mm] = av.y;
        As[kk + 2][mm] = av.z; As[kk + 3][mm] = av.w;
        Bs[kk + 0][mm] = bv.x; Bs[kk + 1][mm] = bv.y;
        Bs[kk + 2][mm] = bv.z; Bs[kk + 3][mm] = bv.w;
        __syncthreads();
#pragma unroll
        for (int k = 0; k < 16; k++) {
            float4 a4 = *(const float4*)&As[k][ty * 4];
            float4 b4 = *(const float4*)&Bs[k][tx * 4];
            float aa[4] = {a4.x, a4.y, a4.z, a4.w};
            float bb[4] = {b4.x, b4.y, b4.z, b4.w};
#pragma unroll
            for (int u = 0; u < 4; u++)
#pragma unroll
                for (int v = 0; v < 4; v++)
                    acc[u][v] = fmaf(aa[u], bb[v], acc[u][v]);
        }
        __syncthreads();
    }

#pragma unroll
    for (int u = 0; u < 4; u++) {
        int m = m0 + ty * 4 + u;
#pragma unroll
        for (int v = 0; v < 4; v++) {
            int n = n0 + tx * 4 + v;
            C[(size_t)m * N + n] = acc[u][v] + bias[n];
        }
    }
}

// ---------------------------------------------------------------------------
// 3) Flash attention with fused rel-shift.
//    score[i,j] = 0.125*( qw_i·k_j + qr_i·r_m ),  m = j-i+T-1, valid j<=i,
//    qw = q + rwb, qr = q + rrb = qw + delta,  delta = rrb - rwb.
//    => score = 0.125*( sum_k qw[i][k]*(K[j][k]+R[d][k]) + corr[d] ),
//       corr[d] = sum_k delta[k]*R[d][k],   d = (j-i) - (j0-i0) + 63 in [0,126]
//
//    One CTA per (i-tile, b, n). 256 threads = 16x16, 4x4 micro-tile.
//    Online softmax; probs bounced through smem for the PV GEMM.
// ---------------------------------------------------------------------------
#define QW_OFF  0
#define KS_OFF  (64 * 68)
#define VS_OFF  (2 * 64 * 68)
#define PS_OFF  (3 * 64 * 68)
#define RS_OFF  (4 * 64 * 68)
#define DL_OFF  (4 * 64 * 68 + 64 * 132)
#define CR_OFF  (DL_OFF + 64)
#define SMEM_FLOATS (CR_OFF + 128)

__global__ __launch_bounds__(256, 2)
void k_flash(const float* __restrict__ qkv, const float* __restrict__ rbuf,
             const float* __restrict__ w, float* __restrict__ att) {
    const int combo = blockIdx.x;        // b*NHH + n
    const int b = combo >> 3;
    const int n = combo & 7;
    const int it = (int)gridDim.y - 1 - (int)blockIdx.y;   // big tiles first
    const int i0 = it * BM;

    const int tid = threadIdx.x;
    const int tx = tid & 15, ty = tid >> 4;

    extern __shared__ float sm[];
    float* qwT   = sm + QW_OFF;   // [64][68]  qwT[k][i]
    float* KsT   = sm + KS_OFF;   // [64][68]  KsT[k][j]
    float* Vs    = sm + VS_OFF;   // [64][68]  Vs[j][d]
    float* Ps    = sm + PS_OFF;   // [64][68]  Ps[i][j]
    float* RsT   = sm + RS_OFF;   // [64][132] RsT[k][d]
    float* delta = sm + DL_OFF;   // [64]
    float* corr  = sm + CR_OFF;   // [128]

    if (tid < 64)
        delta[tid] = w[OFF_RRB + n * HDD + tid] - w[OFF_RWB + n * HDD + tid];

    // load qw tile (transposed) once
    for (int idx = tid; idx < 64 * 64; idx += 256) {
        int rr = idx >> 6, k = idx & 63;
        float v = qkv[((size_t)(i0 + rr) * BB + b) * (3 * DD) + n * HDD + k]
                + w[OFF_RWB + n * HDD + k];
        qwT[k * 68 + rr] = v;
    }

    float m_run[4], l_run[4], o[4][4];
#pragma unroll
    for (int u = 0; u < 4; u++) {
        m_run[u] = -1e30f; l_run[u] = 0.f;
#pragma unroll
        for (int v = 0; v < 4; v++) o[u][v] = 0.f;
    }

    for (int jt = 0; jt <= it; jt++) {
        const int j0 = jt * BN;
        __syncthreads();   // prev iter done reading Ks/Vs/Rs/Ps

        // load K (transposed) and V tiles
        for (int idx = tid; idx < 64 * 64; idx += 256) {
            int rr = idx >> 6, k = idx & 63;
            size_t base = ((size_t)(j0 + rr) * BB + b) * (3 * DD) + n * HDD;
            KsT[k * 68 + rr] = qkv[base + DD + k];
            Vs[rr * 68 + k]  = qkv[base + 2 * DD + k];
        }
        // load R band: rows m = m_base + d, d in [0,126]
        const int m_base = j0 - i0 - 63 + (TT - 1);
        for (int idx = tid; idx < 127 * 64; idx += 256) {
            int d = idx >> 6, k = idx & 63;
            int m = m_base + d;
            RsT[k * 132 + d] = (m < TT) ? rbuf[(size_t)m * DD + n * HDD + k] : 0.f;
        }
        __syncthreads();

        // corr[d] = sum_k delta[k] * RsT[k][d]
        if (tid < 127) {
            float s = 0.f;
#pragma unroll 8
            for (int k = 0; k < 64; k++) s = fmaf(delta[k], RsT[k * 132 + tid], s);
            corr[tid] = s;
        }
        __syncthreads();

        // ---- score tile: sacc[u][v] = sum_k qw*(K + R) ----
        float sacc[4][4] = {};
        const float* qp = qwT + 4 * ty;
        const float* kp = KsT + 4 * tx;
        const float* rp = RsT + (4 * tx - 4 * ty + 60);
#pragma unroll 4
        for (int k = 0; k < 64; k++) {
            float4 q4 = *(const float4*)(qp + k * 68);
            float4 k4 = *(const float4*)(kp + k * 68);
            float rr7[7];
#pragma unroll
            for (int t = 0; t < 7; t++) rr7[t] = rp[k * 132 + t];
            float qa[4] = {q4.x, q4.y, q4.z, q4.w};
            float ka[4] = {k4.x, k4.y, k4.z, k4.w};
#pragma unroll
            for (int u = 0; u < 4; u++)
#pragma unroll
                for (int v = 0; v < 4; v++)
                    sacc[u][v] = fmaf(qa[u], ka[v] + rr7[v - u + 3], sacc[u][v]);
        }

        // epilogue: + corr, scale, causal mask
#pragma unroll
        for (int u = 0; u < 4; u++)
#pragma unroll
            for (int v = 0; v < 4; v++) {
                int dIdx = 4 * tx + v - 4 * ty - u + 63;
                float s = (sacc[u][v] + corr[dIdx]) * 0.125f;
                if (j0 + 4 * tx + v > i0 + 4 * ty + u) s = -1e30f;
                sacc[u][v] = s;
            }

        // ---- online softmax ----
#pragma unroll
        for (int u = 0; u < 4; u++) {
            float mloc = fmaxf(fmaxf(sacc[u][0], sacc[u][1]),
                               fmaxf(sacc[u][2], sacc[u][3]));
#pragma unroll
            for (int off = 1; off < 16; off <<= 1)
                mloc = fmaxf(mloc, __shfl_xor_sync(0xffffffffu, mloc, off));
            float m_new = fmaxf(m_run[u], mloc);
            float scale = __expf(m_run[u] - m_new);
            m_run[u] = m_new;
            float ls = 0.f;
#pragma unroll
            for (int v = 0; v < 4; v++) {
                float p = __expf(sacc[u][v] - m_new);
                sacc[u][v] = p;
                ls += p;
            }
#pragma unroll
            for (int off = 1; off < 16; off <<= 1)
                ls += __shfl_xor_sync(0xffffffffu, ls, off);
            l_run[u] = l_run[u] * scale + ls;
#pragma unroll
            for (int v = 0; v < 4; v++) o[u][v] *= scale;
            // write probs row to smem (Ps[i][j])
            *(float4*)&Ps[(4 * ty + u) * 68 + 4 * tx] =
                make_float4(sacc[u][0], sacc[u][1], sacc[u][2], sacc[u][3]);
        }
        __syncthreads();

        // ---- PV: o[u][v] += sum_j Ps[i][j] * Vs[j][d] ----
#pragma unroll 2
        for (int j = 0; j < 64; j++) {
            float4 v4 = *(const float4*)&Vs[j * 68 + 4 * tx];
            float va[4] = {v4.x, v4.y, v4.z, v4.w};
            float pv[4];
#pragma unroll
            for (int u = 0; u < 4; u++) pv[u] = Ps[(4 * ty + u) * 68 + j];
#pragma unroll
            for (int u = 0; u < 4; u++)
#pragma unroll
                for (int v = 0; v < 4; v++)
                    o[u][v] = fmaf(pv[u], va[v], o[u][v]);
        }
    }

    // normalize + write out
#pragma unroll
    for (int u = 0; u < 4; u++) {
        float inv = 1.f / l_run[u];
        int i = i0 + 4 * ty + u;
        float4 ov = make_float4(o[u][0] * inv, o[u][1] * inv,
                                o[u][2] * inv, o[u][3] * inv);
        *(float4*)&att[((size_t)i * BB + b) * DD + n * HDD + 4 * tx] = ov;
    }
}

// ---------------------------------------------------------------------------
// Launch. Inputs (metadata order): input, pos, attn_mask(unused), mu, rho, eps
// ---------------------------------------------------------------------------
extern "C" void kernel_launch(void* const* d_in, const int* in_sizes, int n_in,
                              void* d_out, int out_size) {
    const float* input = (const float*)d_in[0];
    const float* pos   = (const float*)d_in[1];
    const float* mu    = (const float*)d_in[3];
    const float* rho   = (const float*)d_in[4];
    const float* eps   = (const float*)d_in[5];
    float* out = (float*)d_out;

    float *w, *qkv, *r, *att;
    cudaGetSymbolAddress((void**)&w,   g_w);
    cudaGetSymbolAddress((void**)&qkv, g_qkv);
    cudaGetSymbolAddress((void**)&r,   g_r);
    cudaGetSymbolAddress((void**)&att, g_att);

    static bool attr_set = false;
    if (!attr_set) {
        cudaFuncSetAttribute(k_flash, cudaFuncAttributeMaxDynamicSharedMemorySize,
                             SMEM_FLOATS * (int)sizeof(float));
        attr_set = true;
    }

    k_sample_w<<<(N_W + 255) / 256, 256>>>(mu, rho, eps, w, N_W);

    // qkv = input @ in_w^T + in_b      [4096,512]x[1536,512]^T
    k_gemm<<<dim3(1536 / 64, 4096 / 64), 256>>>(input, w + OFF_INW, w + OFF_INB,
                                                qkv, TT * BB, 3 * DD, DD);
    // r = pos @ pos_w^T + pos_b        [2048,512]x[512,512]^T
    k_gemm<<<dim3(512 / 64, 2048 / 64), 256>>>(pos, w + OFF_POSW, w + OFF_POSB,
                                               r, TT, DD, DD);
    // flash attention: grid (b*n combos, i-tiles)
    k_flash<<<dim3(BB * NHH, TT / BM), 256, SMEM_FLOATS * sizeof(float)>>>(
        qkv, r, w, att);

    // out = att @ out_w^T + out_b      [4096,512]x[512,512]^T
    k_gemm<<<dim3(512 / 64, 4096 / 64), 256>>>(att, w + OFF_OUTW, w + OFF_OUTB,
                                               out, TT * BB, DD, DD);
}

// round 3
// speedup vs baseline: 11.2280x; 1.0604x over previous
#include <cuda_runtime.h>
#include <math.h>

// Problem constants
#define TT  2048
#define BB  2
#define DD  512
#define NHH 8
#define HDD 64

#define BM 64
#define BN 64

// flattened weight offsets
#define OFF_INW   0
#define OFF_OUTW  786432
#define OFF_POSW  1048576
#define OFF_INB   1310720
#define OFF_OUTB  1312256
#define OFF_POSB  1312768
#define OFF_RWB   1313280
#define OFF_RRB   1313792
#define N_W       1314304

typedef unsigned long long u64;

// ---- packed fp32x2 helpers (sm_103a FFMA2 path; IEEE-identical per half) ----
__device__ __forceinline__ u64 pk2(float lo, float hi) {
    u64 r; asm("mov.b64 %0, {%1, %2};" : "=l"(r) : "f"(lo), "f"(hi)); return r;
}
__device__ __forceinline__ u64 splat2(float x) { return pk2(x, x); }
__device__ __forceinline__ void upk2(u64 v, float& lo, float& hi) {
    asm("mov.b64 {%0, %1}, %2;" : "=f"(lo), "=f"(hi) : "l"(v));
}
__device__ __forceinline__ u64 ffma2(u64 a, u64 b, u64 c) {
    u64 d; asm("fma.rn.f32x2 %0, %1, %2, %3;" : "=l"(d) : "l"(a), "l"(b), "l"(c));
    return d;
}
__device__ __forceinline__ u64 fmul2(u64 a, u64 b) {
    u64 d; asm("mul.rn.f32x2 %0, %1, %2;" : "=l"(d) : "l"(a), "l"(b)); return d;
}

// Scratch (allocation-free: __device__ globals)
__device__ float g_w[N_W];
__device__ float g_qkv[(size_t)TT * BB * 3 * DD];   // [T,B,3D]
__device__ float g_r[(size_t)TT * DD];              // [T,D]
__device__ float g_att[(size_t)TT * BB * DD];       // [T,B,D]

// ---------------------------------------------------------------------------
// 1) Bayesian weight sample: w = mu + softplus(rho) * eps
// ---------------------------------------------------------------------------
__global__ void k_sample_w(const float* __restrict__ mu,
                           const float* __restrict__ rho,
                           const float* __restrict__ eps,
                           float* __restrict__ w, int n) {
    int i = blockIdx.x * blockDim.x + threadIdx.x;
    if (i < n) {
        float r  = rho[i];
        float sp = (r > 20.f) ? r : log1pf(expf(r));
        w[i] = fmaf(sp, eps[i], mu[i]);
    }
}

// ---------------------------------------------------------------------------
// 2) C[M,N] = A[M,K] @ W[N,K]^T + bias[N]   (fp32; packed f32x2 inner loop)
// ---------------------------------------------------------------------------
__global__ __launch_bounds__(256)
void k_gemm(const float* __restrict__ A, const float* __restrict__ W,
            const float* __restrict__ bias, float* __restrict__ C,
            int M, int N, int K) {
    __shared__ float As[16][68];
    __shared__ float Bs[16][68];
    const int tid = threadIdx.x;
    const int tx = tid & 15, ty = tid >> 4;
    const int m0 = blockIdx.y * 64, n0 = blockIdx.x * 64;
    const int mm = tid >> 2;
    const int kk = (tid & 3) << 2;

    u64 acc2[4][2];
#pragma unroll
    for (int u = 0; u < 4; u++) { acc2[u][0] = 0ull; acc2[u][1] = 0ull; }

    for (int k0 = 0; k0 < K; k0 += 16) {
        float4 av = *(const float4*)(A + (size_t)(m0 + mm) * K + k0 + kk);
        float4 bv = *(const float4*)(W + (size_t)(n0 + mm) * K + k0 + kk);
        As[kk + 0][mm] = av.x; As[kk + 1][mm] = av.y;
        As[kk + 2][mm] = av.z; As[kk + 3][mm] = av.w;
        Bs[kk + 0][mm] = bv.x; Bs[kk + 1][mm] = bv.y;
        Bs[kk + 2][mm] = bv.z; Bs[kk + 3][mm] = bv.w;
        __syncthreads();
#pragma unroll
        for (int k = 0; k < 16; k++) {
            float4 a4 = *(const float4*)&As[k][ty * 4];
            float4 b4 = *(const float4*)&Bs[k][tx * 4];
            u64 b20 = pk2(b4.x, b4.y), b21 = pk2(b4.z, b4.w);
            u64 a0 = splat2(a4.x), a1 = splat2(a4.y);
            u64 a2 = splat2(a4.z), a3 = splat2(a4.w);
            acc2[0][0] = ffma2(a0, b20, acc2[0][0]);
            acc2[0][1] = ffma2(a0, b21, acc2[0][1]);
            acc2[1][0] = ffma2(a1, b20, acc2[1][0]);
            acc2[1][1] = ffma2(a1, b21, acc2[1][1]);
            acc2[2][0] = ffma2(a2, b20, acc2[2][0]);
            acc2[2][1] = ffma2(a2, b21, acc2[2][1]);
            acc2[3][0] = ffma2(a3, b20, acc2[3][0]);
            acc2[3][1] = ffma2(a3, b21, acc2[3][1]);
        }
        __syncthreads();
    }

#pragma unroll
    for (int u = 0; u < 4; u++) {
        int m = m0 + ty * 4 + u;
        float c0, c1, c2, c3;
        upk2(acc2[u][0], c0, c1);
        upk2(acc2[u][1], c2, c3);
        int n = n0 + tx * 4;
        C[(size_t)m * N + n + 0] = c0 + bias[n + 0];
        C[(size_t)m * N + n + 1] = c1 + bias[n + 1];
        C[(size_t)m * N + n + 2] = c2 + bias[n + 2];
        C[(size_t)m * N + n + 3] = c3 + bias[n + 3];
    }
}

// ---------------------------------------------------------------------------
// 3) Flash attention with fused rel-shift (packed f32x2 math).
//    score[i,j] = 0.125*( qw_i·k_j + qw_i·r_d + corr[d] ),
//    d = (j-i) - (j0-i0) + 63, corr[d] = delta·r_d, delta = rrb - rwb.
// ---------------------------------------------------------------------------
#define QW_OFF  0
#define KS_OFF  (64 * 68)
#define VS_OFF  (2 * 64 * 68)
#define PS_OFF  (3 * 64 * 68)
#define RS_OFF  (4 * 64 * 68)
#define DL_OFF  (4 * 64 * 68 + 64 * 132)
#define CR_OFF  (DL_OFF + 64)
#define SMEM_FLOATS (CR_OFF + 128)

__global__ __launch_bounds__(256, 2)
void k_flash(const float* __restrict__ qkv, const float* __restrict__ rbuf,
             const float* __restrict__ w, float* __restrict__ att) {
    const int combo = blockIdx.x;        // b*NHH + n
    const int b = combo >> 3;
    const int n = combo & 7;
    const int it = (int)gridDim.y - 1 - (int)blockIdx.y;   // big tiles first
    const int i0 = it * BM;

    const int tid = threadIdx.x;
    const int tx = tid & 15, ty = tid >> 4;

    extern __shared__ float sm[];
    float* qwT   = sm + QW_OFF;   // [64][68]  qwT[k][i]
    float* KsT   = sm + KS_OFF;   // [64][68]  KsT[k][j]
    float* Vs    = sm + VS_OFF;   // [64][68]  Vs[j][d]
    float* Ps    = sm + PS_OFF;   // [64][68]  Ps[i][j]
    float* RsT   = sm + RS_OFF;   // [64][132] RsT[k][d]
    float* delta = sm + DL_OFF;   // [64]
    float* corr  = sm + CR_OFF;   // [128]

    if (tid < 64)
        delta[tid] = w[OFF_RRB + n * HDD + tid] - w[OFF_RWB + n * HDD + tid];

    // load qw tile (transposed) once
    for (int idx = tid; idx < 64 * 64; idx += 256) {
        int rr = idx >> 6, k = idx & 63;
        float v = qkv[((size_t)(i0 + rr) * BB + b) * (3 * DD) + n * HDD + k]
                + w[OFF_RWB + n * HDD + k];
        qwT[k * 68 + rr] = v;
    }

    float m_run[4], l_run[4];
    u64 o2[4][2];
#pragma unroll
    for (int u = 0; u < 4; u++) {
        m_run[u] = -1e30f; l_run[u] = 0.f;
        o2[u][0] = 0ull; o2[u][1] = 0ull;
    }

    for (int jt = 0; jt <= it; jt++) {
        const int j0 = jt * BN;
        __syncthreads();   // prev iter done reading Ks/Vs/Rs/Ps

        // load K (transposed) and V tiles
        for (int idx = tid; idx < 64 * 64; idx += 256) {
            int rr = idx >> 6, k = idx & 63;
            size_t base = ((size_t)(j0 + rr) * BB + b) * (3 * DD) + n * HDD;
            KsT[k * 68 + rr] = qkv[base + DD + k];
            Vs[rr * 68 + k]  = qkv[base + 2 * DD + k];
        }
        // load R band: rows m = m_base + d, d in [0,126]
        const int m_base = j0 - i0 - 63 + (TT - 1);
        for (int idx = tid; idx < 127 * 64; idx += 256) {
            int d = idx >> 6, k = idx & 63;
            int m = m_base + d;
            RsT[k * 132 + d] = (m < TT) ? rbuf[(size_t)m * DD + n * HDD + k] : 0.f;
        }
        __syncthreads();

        // corr[d] = sum_k delta[k] * RsT[k][d]
        if (tid < 127) {
            float s = 0.f;
#pragma unroll 8
            for (int k = 0; k < 64; k++) s = fmaf(delta[k], RsT[k * 132 + tid], s);
            corr[tid] = s;
        }
        __syncthreads();

        // ---- score tile (packed): s2[u][v2] = sum_k qw*(K) + qw*(R) ----
        u64 s2[4][2];
#pragma unroll
        for (int u = 0; u < 4; u++) { s2[u][0] = 0ull; s2[u][1] = 0ull; }

        const float4* qp = (const float4*)(qwT + 4 * ty);      // stride 17 float4
        const float4* kp = (const float4*)(KsT + 4 * tx);      // stride 17 float4
        const float4* rp = (const float4*)(RsT + (4 * tx - 4 * ty + 60)); // stride 33

#pragma unroll 4
        for (int k = 0; k < 64; k++) {
            float4 q4 = qp[k * 17];
            float4 k4 = kp[k * 17];
            float4 r0 = rp[k * 33];
            float4 r1 = rp[k * 33 + 1];
            u64 kk0 = pk2(k4.x, k4.y), kk1 = pk2(k4.z, k4.w);
            u64 r01 = pk2(r0.x, r0.y), r12 = pk2(r0.y, r0.z);
            u64 r23 = pk2(r0.z, r0.w), r34 = pk2(r0.w, r1.x);
            u64 r45 = pk2(r1.x, r1.y), r56 = pk2(r1.y, r1.z);
            u64 q0 = splat2(q4.x), q1 = splat2(q4.y);
            u64 q2 = splat2(q4.z), q3 = splat2(q4.w);
            // q·k
            s2[0][0] = ffma2(q0, kk0, s2[0][0]); s2[0][1] = ffma2(q0, kk1, s2[0][1]);
            s2[1][0] = ffma2(q1, kk0, s2[1][0]); s2[1][1] = ffma2(q1, kk1, s2[1][1]);
            s2[2][0] = ffma2(q2, kk0, s2[2][0]); s2[2][1] = ffma2(q2, kk1, s2[2][1]);
            s2[3][0] = ffma2(q3, kk0, s2[3][0]); s2[3][1] = ffma2(q3, kk1, s2[3][1]);
            // q·r, rr[v-u+3]
            s2[0][0] = ffma2(q0, r34, s2[0][0]); s2[0][1] = ffma2(q0, r56, s2[0][1]);
            s2[1][0] = ffma2(q1, r23, s2[1][0]); s2[1][1] = ffma2(q1, r45, s2[1][1]);
            s2[2][0] = ffma2(q2, r12, s2[2][0]); s2[2][1] = ffma2(q2, r34, s2[2][1]);
            s2[3][0] = ffma2(q3, r01, s2[3][0]); s2[3][1] = ffma2(q3, r23, s2[3][1]);
        }

        // epilogue: unpack, + corr, scale, causal mask
        float sv[4][4];
#pragma unroll
        for (int u = 0; u < 4; u++) {
            upk2(s2[u][0], sv[u][0], sv[u][1]);
            upk2(s2[u][1], sv[u][2], sv[u][3]);
#pragma unroll
            for (int v = 0; v < 4; v++) {
                int dIdx = 4 * tx + v - 4 * ty - u + 63;
                float s = (sv[u][v] + corr[dIdx]) * 0.125f;
                if (j0 + 4 * tx + v > i0 + 4 * ty + u) s = -1e30f;
                sv[u][v] = s;
            }
        }

        // ---- online softmax ----
#pragma unroll
        for (int u = 0; u < 4; u++) {
            float mloc = fmaxf(fmaxf(sv[u][0], sv[u][1]),
                               fmaxf(sv[u][2], sv[u][3]));
#pragma unroll
            for (int off = 1; off < 16; off <<= 1)
                mloc = fmaxf(mloc, __shfl_xor_sync(0xffffffffu, mloc, off));
            float m_new = fmaxf(m_run[u], mloc);
            float scale = __expf(m_run[u] - m_new);
            m_run[u] = m_new;
            float ls = 0.f;
#pragma unroll
            for (int v = 0; v < 4; v++) {
                float p = __expf(sv[u][v] - m_new);
                sv[u][v] = p;
                ls += p;
            }
#pragma unroll
            for (int off = 1; off < 16; off <<= 1)
                ls += __shfl_xor_sync(0xffffffffu, ls, off);
            l_run[u] = l_run[u] * scale + ls;
            u64 sc2 = splat2(scale);
            o2[u][0] = fmul2(o2[u][0], sc2);
            o2[u][1] = fmul2(o2[u][1], sc2);
            *(float4*)&Ps[(4 * ty + u) * 68 + 4 * tx] =
                make_float4(sv[u][0], sv[u][1], sv[u][2], sv[u][3]);
        }
        __syncthreads();

        // ---- PV (packed): o2[u][v2] += Ps[i][j] * Vs[j][v2] ----
#pragma unroll 4
        for (int j = 0; j < 64; j++) {
            float4 v4 = *(const float4*)&Vs[j * 68 + 4 * tx];
            u64 vv0 = pk2(v4.x, v4.y), vv1 = pk2(v4.z, v4.w);
            float p0 = Ps[(4 * ty + 0) * 68 + j];
            float p1 = Ps[(4 * ty + 1) * 68 + j];
            float p2 = Ps[(4 * ty + 2) * 68 + j];
            float p3 = Ps[(4 * ty + 3) * 68 + j];
            o2[0][0] = ffma2(splat2(p0), vv0, o2[0][0]);
            o2[0][1] = ffma2(splat2(p0), vv1, o2[0][1]);
            o2[1][0] = ffma2(splat2(p1), vv0, o2[1][0]);
            o2[1][1] = ffma2(splat2(p1), vv1, o2[1][1]);
            o2[2][0] = ffma2(splat2(p2), vv0, o2[2][0]);
            o2[2][1] = ffma2(splat2(p2), vv1, o2[2][1]);
            o2[3][0] = ffma2(splat2(p3), vv0, o2[3][0]);
            o2[3][1] = ffma2(splat2(p3), vv1, o2[3][1]);
        }
    }

    // normalize + write out
#pragma unroll
    for (int u = 0; u < 4; u++) {
        float inv = 1.f / l_run[u];
        int i = i0 + 4 * ty + u;
        float o0, o1, o2_, o3;
        upk2(o2[u][0], o0, o1);
        upk2(o2[u][1], o2_, o3);
        float4 ov = make_float4(o0 * inv, o1 * inv, o2_ * inv, o3 * inv);
        *(float4*)&att[((size_t)i * BB + b) * DD + n * HDD + 4 * tx] = ov;
    }
}

// ---------------------------------------------------------------------------
// Launch. Inputs (metadata order): input, pos, attn_mask(unused), mu, rho, eps
// ---------------------------------------------------------------------------
extern "C" void kernel_launch(void* const* d_in, const int* in_sizes, int n_in,
                              void* d_out, int out_size) {
    const float* input = (const float*)d_in[0];
    const float* pos   = (const float*)d_in[1];
    const float* mu    = (const float*)d_in[3];
    const float* rho   = (const float*)d_in[4];
    const float* eps   = (const float*)d_in[5];
    float* out = (float*)d_out;

    float *w, *qkv, *r, *att;
    cudaGetSymbolAddress((void**)&w,   g_w);
    cudaGetSymbolAddress((void**)&qkv, g_qkv);
    cudaGetSymbolAddress((void**)&r,   g_r);
    cudaGetSymbolAddress((void**)&att, g_att);

    static bool attr_set = false;
    if (!attr_set) {
        cudaFuncSetAttribute(k_flash, cudaFuncAttributeMaxDynamicSharedMemorySize,
                             SMEM_FLOATS * (int)sizeof(float));
        attr_set = true;
    }

    k_sample_w<<<(N_W + 255) / 256, 256>>>(mu, rho, eps, w, N_W);

    // qkv = input @ in_w^T + in_b      [4096,512]x[1536,512]^T
    k_gemm<<<dim3(1536 / 64, 4096 / 64), 256>>>(input, w + OFF_INW, w + OFF_INB,
                                                qkv, TT * BB, 3 * DD, DD);
    // r = pos @ pos_w^T + pos_b        [2048,512]x[512,512]^T
    k_gemm<<<dim3(512 / 64, 2048 / 64), 256>>>(pos, w + OFF_POSW, w + OFF_POSB,
                                               r, TT, DD, DD);
    // flash attention
    k_flash<<<dim3(BB * NHH, TT / BM), 256, SMEM_FLOATS * sizeof(float)>>>(
        qkv, r, w, att);

    // out = att @ out_w^T + out_b      [4096,512]x[512,512]^T
    k_gemm<<<dim3(512 / 64, 4096 / 64), 256>>>(att, w + OFF_OUTW, w + OFF_OUTB,
                                               out, TT * BB, DD, DD);
}

// round 4
// speedup vs baseline: 11.2912x; 1.0056x over previous
#include <cuda_runtime.h>
#include <math.h>

// Problem constants
#define TT  2048
#define BB  2
#define DD  512
#define NHH 8
#define HDD 64

#define BM 64
#define BN 64

// flattened weight offsets
#define OFF_INW   0
#define OFF_OUTW  786432
#define OFF_POSW  1048576
#define OFF_INB   1310720
#define OFF_OUTB  1312256
#define OFF_POSB  1312768
#define OFF_RWB   1313280
#define OFF_RRB   1313792
#define N_W       1314304

typedef unsigned long long u64;

// ---- packed fp32x2 helpers (sm_103a FFMA2 path; IEEE-identical per half) ----
__device__ __forceinline__ u64 pk2(float lo, float hi) {
    u64 r; asm("mov.b64 %0, {%1, %2};" : "=l"(r) : "f"(lo), "f"(hi)); return r;
}
__device__ __forceinline__ u64 splat2(float x) { return pk2(x, x); }
__device__ __forceinline__ void upk2(u64 v, float& lo, float& hi) {
    asm("mov.b64 {%0, %1}, %2;" : "=f"(lo), "=f"(hi) : "l"(v));
}
__device__ __forceinline__ u64 ffma2(u64 a, u64 b, u64 c) {
    u64 d; asm("fma.rn.f32x2 %0, %1, %2, %3;" : "=l"(d) : "l"(a), "l"(b), "l"(c));
    return d;
}
__device__ __forceinline__ u64 fmul2(u64 a, u64 b) {
    u64 d; asm("mul.rn.f32x2 %0, %1, %2;" : "=l"(d) : "l"(a), "l"(b)); return d;
}

// Scratch (allocation-free: __device__ globals)
__device__ float g_w[N_W];
__device__ float g_qkv[(size_t)TT * BB * 3 * DD];   // [T,B,3D]
__device__ float g_r[(size_t)TT * DD];              // [T,D]
__device__ float g_att[(size_t)TT * BB * DD];       // [T,B,D]

// ---------------------------------------------------------------------------
// 1) Bayesian weight sample: w = mu + softplus(rho) * eps
// ---------------------------------------------------------------------------
__global__ void k_sample_w(const float* __restrict__ mu,
                           const float* __restrict__ rho,
                           const float* __restrict__ eps,
                           float* __restrict__ w, int n) {
    int i = blockIdx.x * blockDim.x + threadIdx.x;
    if (i < n) {
        float r  = rho[i];
        float sp = (r > 20.f) ? r : log1pf(expf(r));
        w[i] = fmaf(sp, eps[i], mu[i]);
    }
}

// ---------------------------------------------------------------------------
// 2) C[M,N] = A[M,K] @ W[N,K]^T + bias[N]   (fp32; packed f32x2 inner loop)
// ---------------------------------------------------------------------------
__global__ __launch_bounds__(256)
void k_gemm(const float* __restrict__ A, const float* __restrict__ W,
            const float* __restrict__ bias, float* __restrict__ C,
            int M, int N, int K) {
    __shared__ float As[16][68];
    __shared__ float Bs[16][68];
    const int tid = threadIdx.x;
    const int tx = tid & 15, ty = tid >> 4;
    const int m0 = blockIdx.y * 64, n0 = blockIdx.x * 64;
    const int mm = tid >> 2;
    const int kk = (tid & 3) << 2;

    u64 acc2[4][2];
#pragma unroll
    for (int u = 0; u < 4; u++) { acc2[u][0] = 0ull; acc2[u][1] = 0ull; }

    for (int k0 = 0; k0 < K; k0 += 16) {
        float4 av = *(const float4*)(A + (size_t)(m0 + mm) * K + k0 + kk);
        float4 bv = *(const float4*)(W + (size_t)(n0 + mm) * K + k0 + kk);
        As[kk + 0][mm] = av.x; As[kk + 1][mm] = av.y;
        As[kk + 2][mm] = av.z; As[kk + 3][mm] = av.w;
        Bs[kk + 0][mm] = bv.x; Bs[kk + 1][mm] = bv.y;
        Bs[kk + 2][mm] = bv.z; Bs[kk + 3][mm] = bv.w;
        __syncthreads();
#pragma unroll
        for (int k = 0; k < 16; k++) {
            float4 a4 = *(const float4*)&As[k][ty * 4];
            float4 b4 = *(const float4*)&Bs[k][tx * 4];
            u64 b20 = pk2(b4.x, b4.y), b21 = pk2(b4.z, b4.w);
            u64 a0 = splat2(a4.x), a1 = splat2(a4.y);
            u64 a2 = splat2(a4.z), a3 = splat2(a4.w);
            acc2[0][0] = ffma2(a0, b20, acc2[0][0]);
            acc2[0][1] = ffma2(a0, b21, acc2[0][1]);
            acc2[1][0] = ffma2(a1, b20, acc2[1][0]);
            acc2[1][1] = ffma2(a1, b21, acc2[1][1]);
            acc2[2][0] = ffma2(a2, b20, acc2[2][0]);
            acc2[2][1] = ffma2(a2, b21, acc2[2][1]);
            acc2[3][0] = ffma2(a3, b20, acc2[3][0]);
            acc2[3][1] = ffma2(a3, b21, acc2[3][1]);
        }
        __syncthreads();
    }

#pragma unroll
    for (int u = 0; u < 4; u++) {
        int m = m0 + ty * 4 + u;
        float c0, c1, c2, c3;
        upk2(acc2[u][0], c0, c1);
        upk2(acc2[u][1], c2, c3);
        int n = n0 + tx * 4;
        C[(size_t)m * N + n + 0] = c0 + bias[n + 0];
        C[(size_t)m * N + n + 1] = c1 + bias[n + 1];
        C[(size_t)m * N + n + 2] = c2 + bias[n + 2];
        C[(size_t)m * N + n + 3] = c3 + bias[n + 3];
    }
}

// ---------------------------------------------------------------------------
// 3) Flash attention with fused rel-shift (packed f32x2 math).
//    score[i,j] = 0.125*( qw_i·k_j + qw_i·r_d + corr[d] ),
//    d = (j-i) - (j0-i0) + 63, corr[d] = delta·r_d, delta = rrb - rwb.
// ---------------------------------------------------------------------------
#define QW_OFF  0
#define KS_OFF  (64 * 68)
#define VS_OFF  (2 * 64 * 68)
#define PS_OFF  (3 * 64 * 68)
#define RS_OFF  (4 * 64 * 68)
#define DL_OFF  (4 * 64 * 68 + 64 * 132)
#define CR_OFF  (DL_OFF + 64)
#define SMEM_FLOATS (CR_OFF + 128)

__global__ __launch_bounds__(256, 2)
void k_flash(const float* __restrict__ qkv, const float* __restrict__ rbuf,
             const float* __restrict__ w, float* __restrict__ att) {
    const int combo = blockIdx.x;        // b*NHH + n
    const int b = combo >> 3;
    const int n = combo & 7;
    const int it = (int)gridDim.y - 1 - (int)blockIdx.y;   // big tiles first
    const int i0 = it * BM;

    const int tid = threadIdx.x;
    const int tx = tid & 15, ty = tid >> 4;

    extern __shared__ float sm[];
    float* qwT   = sm + QW_OFF;   // [64][68]  qwT[k][i]
    float* KsT   = sm + KS_OFF;   // [64][68]  KsT[k][j]
    float* Vs    = sm + VS_OFF;   // [64][68]  Vs[j][d]
    float* Ps    = sm + PS_OFF;   // [64][68]  Ps[i][j]
    float* RsT   = sm + RS_OFF;   // [64][132] RsT[k][d]
    float* delta = sm + DL_OFF;   // [64]
    float* corr  = sm + CR_OFF;   // [128]

    if (tid < 64)
        delta[tid] = w[OFF_RRB + n * HDD + tid] - w[OFF_RWB + n * HDD + tid];

    // load qw tile (transposed) once
    for (int idx = tid; idx < 64 * 64; idx += 256) {
        int rr = idx >> 6, k = idx & 63;
        float v = qkv[((size_t)(i0 + rr) * BB + b) * (3 * DD) + n * HDD + k]
                + w[OFF_RWB + n * HDD + k];
        qwT[k * 68 + rr] = v;
    }

    float m_run[4], l_run[4];
    u64 o2[4][2];
#pragma unroll
    for (int u = 0; u < 4; u++) {
        m_run[u] = -1e30f; l_run[u] = 0.f;
        o2[u][0] = 0ull; o2[u][1] = 0ull;
    }

    for (int jt = 0; jt <= it; jt++) {
        const int j0 = jt * BN;
        __syncthreads();   // prev iter done reading Ks/Vs/Rs/Ps

        // load K (transposed) and V tiles
        for (int idx = tid; idx < 64 * 64; idx += 256) {
            int rr = idx >> 6, k = idx & 63;
            size_t base = ((size_t)(j0 + rr) * BB + b) * (3 * DD) + n * HDD;
            KsT[k * 68 + rr] = qkv[base + DD + k];
            Vs[rr * 68 + k]  = qkv[base + 2 * DD + k];
        }
        // load R band: rows m = m_base + d, d in [0,126]
        const int m_base = j0 - i0 - 63 + (TT - 1);
        for (int idx = tid; idx < 127 * 64; idx += 256) {
            int d = idx >> 6, k = idx & 63;
            int m = m_base + d;
            RsT[k * 132 + d] = (m < TT) ? rbuf[(size_t)m * DD + n * HDD + k] : 0.f;
        }
        __syncthreads();

        // corr[d] = sum_k delta[k] * RsT[k][d]
        if (tid < 127) {
            float s = 0.f;
#pragma unroll 8
            for (int k = 0; k < 64; k++) s = fmaf(delta[k], RsT[k * 132 + tid], s);
            corr[tid] = s;
        }
        __syncthreads();

        // ---- score tile (packed): s2[u][v2] = sum_k qw*(K) + qw*(R) ----
        u64 s2[4][2];
#pragma unroll
        for (int u = 0; u < 4; u++) { s2[u][0] = 0ull; s2[u][1] = 0ull; }

        const float4* qp = (const float4*)(qwT + 4 * ty);      // stride 17 float4
        const float4* kp = (const float4*)(KsT + 4 * tx);      // stride 17 float4
        const float4* rp = (const float4*)(RsT + (4 * tx - 4 * ty + 60)); // stride 33

#pragma unroll 4
        for (int k = 0; k < 64; k++) {
            float4 q4 = qp[k * 17];
            float4 k4 = kp[k * 17];
            float4 r0 = rp[k * 33];
            float4 r1 = rp[k * 33 + 1];
            u64 kk0 = pk2(k4.x, k4.y), kk1 = pk2(k4.z, k4.w);
            u64 r01 = pk2(r0.x, r0.y), r12 = pk2(r0.y, r0.z);
            u64 r23 = pk2(r0.z, r0.w), r34 = pk2(r0.w, r1.x);
            u64 r45 = pk2(r1.x, r1.y), r56 = pk2(r1.y, r1.z);
            u64 q0 = splat2(q4.x), q1 = splat2(q4.y);
            u64 q2 = splat2(q4.z), q3 = splat2(q4.w);
            // q·k
            s2[0][0] = ffma2(q0, kk0, s2[0][0]); s2[0][1] = ffma2(q0, kk1, s2[0][1]);
            s2[1][0] = ffma2(q1, kk0, s2[1][0]); s2[1][1] = ffma2(q1, kk1, s2[1][1]);
            s2[2][0] = ffma2(q2, kk0, s2[2][0]); s2[2][1] = ffma2(q2, kk1, s2[2][1]);
            s2[3][0] = ffma2(q3, kk0, s2[3][0]); s2[3][1] = ffma2(q3, kk1, s2[3][1]);
            // q·r, rr[v-u+3]
            s2[0][0] = ffma2(q0, r34, s2[0][0]); s2[0][1] = ffma2(q0, r56, s2[0][1]);
            s2[1][0] = ffma2(q1, r23, s2[1][0]); s2[1][1] = ffma2(q1, r45, s2[1][1]);
            s2[2][0] = ffma2(q2, r12, s2[2][0]); s2[2][1] = ffma2(q2, r34, s2[2][1]);
            s2[3][0] = ffma2(q3, r01, s2[3][0]); s2[3][1] = ffma2(q3, r23, s2[3][1]);
        }

        // epilogue: unpack, + corr, scale, causal mask
        float sv[4][4];
#pragma unroll
        for (int u = 0; u < 4; u++) {
            upk2(s2[u][0], sv[u][0], sv[u][1]);
            upk2(s2[u][1], sv[u][2], sv[u][3]);
#pragma unroll
            for (int v = 0; v < 4; v++) {
                int dIdx = 4 * tx + v - 4 * ty - u + 63;
                float s = (sv[u][v] + corr[dIdx]) * 0.125f;
                if (j0 + 4 * tx + v > i0 + 4 * ty + u) s = -1e30f;
                sv[u][v] = s;
            }
        }

        // ---- online softmax ----
#pragma unroll
        for (int u = 0; u < 4; u++) {
            float mloc = fmaxf(fmaxf(sv[u][0], sv[u][1]),
                               fmaxf(sv[u][2], sv[u][3]));
#pragma unroll
            for (int off = 1; off < 16; off <<= 1)
                mloc = fmaxf(mloc, __shfl_xor_sync(0xffffffffu, mloc, off));
            float m_new = fmaxf(m_run[u], mloc);
            float scale = __expf(m_run[u] - m_new);
            m_run[u] = m_new;
            float ls = 0.f;
#pragma unroll
            for (int v = 0; v < 4; v++) {
                float p = __expf(sv[u][v] - m_new);
                sv[u][v] = p;
                ls += p;
            }
#pragma unroll
            for (int off = 1; off < 16; off <<= 1)
                ls += __shfl_xor_sync(0xffffffffu, ls, off);
            l_run[u] = l_run[u] * scale + ls;
            u64 sc2 = splat2(scale);
            o2[u][0] = fmul2(o2[u][0], sc2);
            o2[u][1] = fmul2(o2[u][1], sc2);
            *(float4*)&Ps[(4 * ty + u) * 68 + 4 * tx] =
                make_float4(sv[u][0], sv[u][1], sv[u][2], sv[u][3]);
        }
        __syncthreads();

        // ---- PV (packed): o2[u][v2] += Ps[i][j] * Vs[j][v2] ----
#pragma unroll 4
        for (int j = 0; j < 64; j++) {
            float4 v4 = *(const float4*)&Vs[j * 68 + 4 * tx];
            u64 vv0 = pk2(v4.x, v4.y), vv1 = pk2(v4.z, v4.w);
            float p0 = Ps[(4 * ty + 0) * 68 + j];
            float p1 = Ps[(4 * ty + 1) * 68 + j];
            float p2 = Ps[(4 * ty + 2) * 68 + j];
            float p3 = Ps[(4 * ty + 3) * 68 + j];
            o2[0][0] = ffma2(splat2(p0), vv0, o2[0][0]);
            o2[0][1] = ffma2(splat2(p0), vv1, o2[0][1]);
            o2[1][0] = ffma2(splat2(p1), vv0, o2[1][0]);
            o2[1][1] = ffma2(splat2(p1), vv1, o2[1][1]);
            o2[2][0] = ffma2(splat2(p2), vv0, o2[2][0]);
            o2[2][1] = ffma2(splat2(p2), vv1, o2[2][1]);
            o2[3][0] = ffma2(splat2(p3), vv0, o2[3][0]);
            o2[3][1] = ffma2(splat2(p3), vv1, o2[3][1]);
        }
    }

    // normalize + write out
#pragma unroll
    for (int u = 0; u < 4; u++) {
        float inv = 1.f / l_run[u];
        int i = i0 + 4 * ty + u;
        float o0, o1, o2_, o3;
        upk2(o2[u][0], o0, o1);
        upk2(o2[u][1], o2_, o3);
        float4 ov = make_float4(o0 * inv, o1 * inv, o2_ * inv, o3 * inv);
        *(float4*)&att[((size_t)i * BB + b) * DD + n * HDD + 4 * tx] = ov;
    }
}

// ---------------------------------------------------------------------------
// Launch. Inputs (metadata order): input, pos, attn_mask(unused), mu, rho, eps
// ---------------------------------------------------------------------------
extern "C" void kernel_launch(void* const* d_in, const int* in_sizes, int n_in,
                              void* d_out, int out_size) {
    const float* input = (const float*)d_in[0];
    const float* pos   = (const float*)d_in[1];
    const float* mu    = (const float*)d_in[3];
    const float* rho   = (const float*)d_in[4];
    const float* eps   = (const float*)d_in[5];
    float* out = (float*)d_out;

    float *w, *qkv, *r, *att;
    cudaGetSymbolAddress((void**)&w,   g_w);
    cudaGetSymbolAddress((void**)&qkv, g_qkv);
    cudaGetSymbolAddress((void**)&r,   g_r);
    cudaGetSymbolAddress((void**)&att, g_att);

    static bool attr_set = false;
    if (!attr_set) {
        cudaFuncSetAttribute(k_flash, cudaFuncAttributeMaxDynamicSharedMemorySize,
                             SMEM_FLOATS * (int)sizeof(float));
        attr_set = true;
    }

    k_sample_w<<<(N_W + 255) / 256, 256>>>(mu, rho, eps, w, N_W);

    // qkv = input @ in_w^T + in_b      [4096,512]x[1536,512]^T
    k_gemm<<<dim3(1536 / 64, 4096 / 64), 256>>>(input, w + OFF_INW, w + OFF_INB,
                                                qkv, TT * BB, 3 * DD, DD);
    // r = pos @ pos_w^T + pos_b        [2048,512]x[512,512]^T
    k_gemm<<<dim3(512 / 64, 2048 / 64), 256>>>(pos, w + OFF_POSW, w + OFF_POSB,
                                               r, TT, DD, DD);
    // flash attention
    k_flash<<<dim3(BB * NHH, TT / BM), 256, SMEM_FLOATS * sizeof(float)>>>(
        qkv, r, w, att);

    // out = att @ out_w^T + out_b      [4096,512]x[512,512]^T
    k_gemm<<<dim3(512 / 64, 4096 / 64), 256>>>(att, w + OFF_OUTW, w + OFF_OUTB,
                                               out, TT * BB, DD, DD);
}

// round 5
// speedup vs baseline: 12.3302x; 1.0920x over previous
#include <cuda_runtime.h>
#include <math.h>

#define TT  2048
#define BB  2
#define DD  512
#define NHH 8

#define OFF_INW   0
#define OFF_OUTW  786432
#define OFF_POSW  1048576
#define OFF_INB   1310720
#define OFF_OUTB  1312256
#define OFF_POSB  1312768
#define OFF_RWB   1313280
#define OFF_RRB   1313792
#define N_W       1314304

typedef unsigned long long u64;

__device__ __forceinline__ void upk2(u64 v, float& lo, float& hi) {
    asm("mov.b64 {%0, %1}, %2;" : "=f"(lo), "=f"(hi) : "l"(v));
}
__device__ __forceinline__ u64 ffma2(u64 a, u64 b, u64 c) {
    u64 d; asm("fma.rn.f32x2 %0, %1, %2, %3;" : "=l"(d) : "l"(a), "l"(b), "l"(c));
    return d;
}
__device__ __forceinline__ u64 fmul2(u64 a, u64 b) {
    u64 d; asm("mul.rn.f32x2 %0, %1, %2;" : "=l"(d) : "l"(a), "l"(b)); return d;
}
__device__ __forceinline__ u64 splat2(float x) {
    u64 r; asm("mov.b64 %0, {%1, %1};" : "=l"(r) : "f"(x)); return r;
}
__device__ __forceinline__ u64 pk2(float lo, float hi) {
    u64 r; asm("mov.b64 %0, {%1, %2};" : "=l"(r) : "f"(lo), "f"(hi)); return r;
}

__device__ float g_w[N_W];
__device__ float g_qkv[(size_t)TT * BB * 3 * DD];
__device__ float g_r[(size_t)TT * DD];
__device__ float g_att[(size_t)TT * BB * DD];

// ---------------------------------------------------------------------------
__global__ void k_sample_w(const float* __restrict__ mu,
                           const float* __restrict__ rho,
                           const float* __restrict__ eps,
                           float* __restrict__ w, int n) {
    int i = blockIdx.x * blockDim.x + threadIdx.x;
    if (i < n) {
        float r = rho[i];
        float sp = (r > 20.f) ? r : log1pf(expf(r));
        w[i] = fmaf(sp, eps[i], mu[i]);
    }
}

// ---------------------------------------------------------------------------
// GEMM: C[M,N] = A[M,K] @ W[N,K]^T + bias. 64x64 tile, 64-wide K stages,
// k-packed FFMA2, XOR-swizzled Bs. M,N %64==0, K %64==0.
// ---------------------------------------------------------------------------
__global__ __launch_bounds__(256)
void k_gemm(const float* __restrict__ A, const float* __restrict__ W,
            const float* __restrict__ bias, float* __restrict__ C,
            int M, int N, int K) {
    __shared__ float As[64 * 64];
    __shared__ float Bs[64 * 64];
    const int tid = threadIdx.x, tx = tid & 15, ty = tid >> 4;
    const int m0 = blockIdx.y * 64, n0 = blockIdx.x * 64;

    u64 acc[4][4];
#pragma unroll
    for (int u = 0; u < 4; u++)
#pragma unroll
        for (int v = 0; v < 4; v++) acc[u][v] = 0ull;

    for (int k0 = 0; k0 < K; k0 += 64) {
        __syncthreads();
#pragma unroll
        for (int p = 0; p < 4; p++) {
            int idx = p * 256 + tid;
            int mi = idx >> 4, k4 = idx & 15;
            *(float4*)(As + mi * 64 + 4 * k4) =
                *(const float4*)(A + (size_t)(m0 + mi) * K + k0 + 4 * k4);
            *(float4*)(Bs + mi * 64 + 4 * (k4 ^ (mi >> 2))) =
                *(const float4*)(W + (size_t)(n0 + mi) * K + k0 + 4 * k4);
        }
        __syncthreads();
        const float* ab = As + 4 * ty * 64;
        const float* bb = Bs + 4 * tx * 64;
#pragma unroll 4
        for (int k4 = 0; k4 < 16; k4++) {
            ulonglong2 av[4], bv[4];
#pragma unroll
            for (int u = 0; u < 4; u++)
                av[u] = *(const ulonglong2*)(ab + u * 64 + 4 * k4);
            int sk = 4 * (k4 ^ tx);
#pragma unroll
            for (int v = 0; v < 4; v++)
                bv[v] = *(const ulonglong2*)(bb + v * 64 + sk);
#pragma unroll
            for (int u = 0; u < 4; u++)
#pragma unroll
                for (int v = 0; v < 4; v++) {
                    acc[u][v] = ffma2(av[u].x, bv[v].x, acc[u][v]);
                    acc[u][v] = ffma2(av[u].y, bv[v].y, acc[u][v]);
                }
        }
    }

    float4 b4 = *(const float4*)(bias + n0 + 4 * tx);
#pragma unroll
    for (int u = 0; u < 4; u++) {
        float c[4];
#pragma unroll
        for (int v = 0; v < 4; v++) {
            float lo, hi; upk2(acc[u][v], lo, hi);
            c[v] = lo + hi;
        }
        *(float4*)(C + (size_t)(m0 + 4 * ty + u) * N + n0 + 4 * tx) =
            make_float4(c[0] + b4.x, c[1] + b4.y, c[2] + b4.z, c[3] + b4.w);
    }
}

// ---------------------------------------------------------------------------
// Flash attention, fused rel-shift, k-packed FFMA2, swizzled K/R tiles.
// score[i,j] = 0.125*( qw_i·k_j + qw_i·r_dd + corr[dd] ), dd = j-i+63 (tile),
// corr[dd] = delta·r_dd, delta = rrb - rwb. 64x64 tiles, 256 thr, 4x4 micro.
// ---------------------------------------------------------------------------
#define QWS 0
#define KSS 4096
#define VSS 8192
#define PSS 12544
#define RSS 16896
#define DLS 25024
#define CRS 25088
#define SMF 25216   // floats (100864 bytes)

__global__ __launch_bounds__(256, 2)
void k_flash(const float* __restrict__ qkv, const float* __restrict__ rbuf,
             const float* __restrict__ w, float* __restrict__ att) {
    const int combo = blockIdx.x, b = combo >> 3, n = combo & 7;
    const int it = (int)gridDim.y - 1 - (int)blockIdx.y;
    const int i0 = it * 64;
    const int tid = threadIdx.x, tx = tid & 15, ty = tid >> 4;

    extern __shared__ float sm[];
    float* qws = sm + QWS;   // [64][64] q+rwb, row-major
    float* Ks  = sm + KSS;   // [64][64] swizzled k-cols
    float* Vs  = sm + VSS;   // [64][68]
    float* Ps  = sm + PSS;   // [64][68]
    float* Rs  = sm + RSS;   // [127][64] swizzled k-cols
    float* delta = sm + DLS;
    float* corr  = sm + CRS;

    if (tid < 64)
        delta[tid] = w[OFF_RRB + n * 64 + tid] - w[OFF_RWB + n * 64 + tid];

#pragma unroll
    for (int p = 0; p < 4; p++) {
        int idx = p * 256 + tid;
        int i = idx >> 4, k4 = idx & 15;
        float4 qv = *(const float4*)(qkv + ((size_t)(i0 + i) * BB + b) * 1536 + n * 64 + 4 * k4);
        float4 bw = *(const float4*)(w + OFF_RWB + n * 64 + 4 * k4);
        *(float4*)(qws + i * 64 + 4 * k4) =
            make_float4(qv.x + bw.x, qv.y + bw.y, qv.z + bw.z, qv.w + bw.w);
    }

    const int ddbase = 4 * (tx - ty) + 60;
    float m_run[4], l_run[4];
    u64 o2[4][2];
#pragma unroll
    for (int u = 0; u < 4; u++) {
        m_run[u] = -1e30f; l_run[u] = 0.f;
        o2[u][0] = 0ull; o2[u][1] = 0ull;
    }

    for (int jt = 0; jt <= it; jt++) {
        const int j0 = jt * 64;
        __syncthreads();

        // stage K (swizzled) + V
#pragma unroll
        for (int p = 0; p < 4; p++) {
            int idx = p * 256 + tid;
            int j = idx >> 4, k4 = idx & 15;
            const float* base = qkv + ((size_t)(j0 + j) * BB + b) * 1536 + n * 64;
            *(float4*)(Ks + j * 64 + 4 * (k4 ^ (j >> 2))) =
                *(const float4*)(base + 512 + 4 * k4);
            *(float4*)(Vs + j * 68 + 4 * k4) = *(const float4*)(base + 1024 + 4 * k4);
        }
        // stage R band rows dd=0..126 (swizzled)
        const int m_base = j0 - i0 + 1984;
        for (int idx = tid; idx < 127 * 16; idx += 256) {
            int dd = idx >> 4, k4 = idx & 15;
            int gm = m_base + dd;
            float4 rv = make_float4(0.f, 0.f, 0.f, 0.f);
            if (gm < TT)
                rv = *(const float4*)(rbuf + (size_t)gm * 512 + n * 64 + 4 * k4);
            *(float4*)(Rs + dd * 64 + 4 * (k4 ^ ((dd >> 2) & 15))) = rv;
        }
        __syncthreads();

        // corr[dd] = delta · r_dd
        if (tid < 127) {
            const float4* rrow = (const float4*)(Rs + tid * 64);
            int key = (tid >> 2) & 15;
            float s = 0.f;
#pragma unroll
            for (int k4 = 0; k4 < 16; k4++) {
                float4 rv = rrow[k4 ^ key];
                float4 dl = ((const float4*)delta)[k4];
                s = fmaf(dl.x, rv.x, s); s = fmaf(dl.y, rv.y, s);
                s = fmaf(dl.z, rv.z, s); s = fmaf(dl.w, rv.w, s);
            }
            corr[tid] = s;
        }
        __syncthreads();

        // ---- score: k-packed, zero movs ----
        u64 s2[4][4];
#pragma unroll
        for (int u = 0; u < 4; u++)
#pragma unroll
            for (int v = 0; v < 4; v++) s2[u][v] = 0ull;

        const float* qb = qws + 4 * ty * 64;
        const float* kb = Ks + 4 * tx * 64;
        const float* rb = Rs + ddbase * 64;
        const int keyA = (ddbase >> 2) & 15;
        const int keyB = ((ddbase >> 2) + 1) & 15;

#pragma unroll 4
        for (int k4 = 0; k4 < 16; k4++) {
            ulonglong2 qv[4], kv[4];
#pragma unroll
            for (int u = 0; u < 4; u++)
                qv[u] = *(const ulonglong2*)(qb + u * 64 + 4 * k4);
            int sk = 4 * (k4 ^ tx);
#pragma unroll
            for (int v = 0; v < 4; v++)
                kv[v] = *(const ulonglong2*)(kb + v * 64 + sk);
#pragma unroll
            for (int u = 0; u < 4; u++)
#pragma unroll
                for (int v = 0; v < 4; v++) {
                    s2[u][v] = ffma2(qv[u].x, kv[v].x, s2[u][v]);
                    s2[u][v] = ffma2(qv[u].y, kv[v].y, s2[u][v]);
                }
            int sA = 4 * (k4 ^ keyA), sB = 4 * (k4 ^ keyB);
#pragma unroll
            for (int t = 0; t < 7; t++) {
                ulonglong2 rv = *(const ulonglong2*)(rb + t * 64 + (t < 4 ? sA : sB));
#pragma unroll
                for (int u = 0; u < 4; u++) {
                    int v = u + t - 3;
                    if (v >= 0 && v < 4) {
                        s2[u][v] = ffma2(qv[u].x, rv.x, s2[u][v]);
                        s2[u][v] = ffma2(qv[u].y, rv.y, s2[u][v]);
                    }
                }
            }
        }

        // ---- epilogue: unpack + corr + scale + mask ----
        float sv[4][4];
#pragma unroll
        for (int u = 0; u < 4; u++)
#pragma unroll
            for (int v = 0; v < 4; v++) {
                float lo, hi; upk2(s2[u][v], lo, hi);
                float s = (lo + hi + corr[ddbase + 3 + v - u]) * 0.125f;
                if (j0 + 4 * tx + v > i0 + 4 * ty + u) s = -1e30f;
                sv[u][v] = s;
            }

        // ---- online softmax ----
#pragma unroll
        for (int u = 0; u < 4; u++) {
            float mloc = fmaxf(fmaxf(sv[u][0], sv[u][1]), fmaxf(sv[u][2], sv[u][3]));
#pragma unroll
            for (int off = 1; off < 16; off <<= 1)
                mloc = fmaxf(mloc, __shfl_xor_sync(0xffffffffu, mloc, off));
            float m_new = fmaxf(m_run[u], mloc);
            float scale = __expf(m_run[u] - m_new);
            m_run[u] = m_new;
            float ls = 0.f;
#pragma unroll
            for (int v = 0; v < 4; v++) {
                float p = __expf(sv[u][v] - m_new);
                sv[u][v] = p;
                ls += p;
            }
#pragma unroll
            for (int off = 1; off < 16; off <<= 1)
                ls += __shfl_xor_sync(0xffffffffu, ls, off);
            l_run[u] = l_run[u] * scale + ls;
            u64 sc2 = splat2(scale);
            o2[u][0] = fmul2(o2[u][0], sc2);
            o2[u][1] = fmul2(o2[u][1], sc2);
            *(float4*)&Ps[(4 * ty + u) * 68 + 4 * tx] =
                make_float4(sv[u][0], sv[u][1], sv[u][2], sv[u][3]);
        }
        __syncthreads();

        // ---- PV ----
#pragma unroll 4
        for (int j = 0; j < 64; j++) {
            float4 v4 = *(const float4*)&Vs[j * 68 + 4 * tx];
            u64 vv0 = pk2(v4.x, v4.y), vv1 = pk2(v4.z, v4.w);
#pragma unroll
            for (int u = 0; u < 4; u++) {
                u64 ps = splat2(Ps[(4 * ty + u) * 68 + j]);
                o2[u][0] = ffma2(ps, vv0, o2[u][0]);
                o2[u][1] = ffma2(ps, vv1, o2[u][1]);
            }
        }
    }

    // ---- normalize + write ----
#pragma unroll
    for (int u = 0; u < 4; u++) {
        float inv = 1.f / l_run[u];
        int i = i0 + 4 * ty + u;
        float a0, a1, a2, a3;
        upk2(o2[u][0], a0, a1);
        upk2(o2[u][1], a2, a3);
        *(float4*)&att[((size_t)i * BB + b) * 512 + n * 64 + 4 * tx] =
            make_float4(a0 * inv, a1 * inv, a2 * inv, a3 * inv);
    }
}

// ---------------------------------------------------------------------------
extern "C" void kernel_launch(void* const* d_in, const int* in_sizes, int n_in,
                              void* d_out, int out_size) {
    const float* input = (const float*)d_in[0];
    const float* pos   = (const float*)d_in[1];
    const float* mu    = (const float*)d_in[3];
    const float* rho   = (const float*)d_in[4];
    const float* eps   = (const float*)d_in[5];
    float* out = (float*)d_out;

    float *w, *qkv, *r, *att;
    cudaGetSymbolAddress((void**)&w,   g_w);
    cudaGetSymbolAddress((void**)&qkv, g_qkv);
    cudaGetSymbolAddress((void**)&r,   g_r);
    cudaGetSymbolAddress((void**)&att, g_att);

    static bool attr_set = false;
    if (!attr_set) {
        cudaFuncSetAttribute(k_flash, cudaFuncAttributeMaxDynamicSharedMemorySize,
                             SMF * (int)sizeof(float));
        attr_set = true;
    }

    k_sample_w<<<(N_W + 255) / 256, 256>>>(mu, rho, eps, w, N_W);

    k_gemm<<<dim3(1536 / 64, 4096 / 64), 256>>>(input, w + OFF_INW, w + OFF_INB,
                                                qkv, TT * BB, 3 * DD, DD);
    k_gemm<<<dim3(512 / 64, 2048 / 64), 256>>>(pos, w + OFF_POSW, w + OFF_POSB,
                                               r, TT, DD, DD);
    k_flash<<<dim3(BB * NHH, 32), 256, SMF * sizeof(float)>>>(qkv, r, w, att);

    k_gemm<<<dim3(512 / 64, 4096 / 64), 256>>>(att, w + OFF_OUTW, w + OFF_OUTB,
                                               out, TT * BB, DD, DD);
}